// round 14
// baseline (speedup 1.0000x reference)
#include <cuda_runtime.h>

#define NN 50000
#define EE 800000
#define NB ((NN + 255) / 256)
#define CAP 96                    // per-node adjacency capacity (P(overflow) ~ e^-41)
#define PJB 300                   // persistent proj blocks
#define WPAD 132                  // padded row stride for transposed weights (bank-safe)

typedef unsigned long long u64;

__device__ __forceinline__ u64 pk2(float lo, float hi) {
    u64 d; asm("mov.b64 %0, {%1,%2};" : "=l"(d) : "f"(lo), "f"(hi)); return d;
}
__device__ __forceinline__ void upk2(u64 v, float& lo, float& hi) {
    asm("mov.b64 {%0,%1}, %2;" : "=f"(lo), "=f"(hi) : "l"(v));
}
__device__ __forceinline__ u64 f2fma(u64 a, u64 b, u64 c) {
    u64 d; asm("fma.rn.f32x2 %0, %1, %2, %3;" : "=l"(d) : "l"(a), "l"(b), "l"(c)); return d;
}

// ---------------- scratch (device globals; no allocation allowed) ----------------
__device__ int    g_is64;               // 1 if edge_index is int64, 0 if int32
__device__ int    g_cnt[NN];            // in-degree (w/o self loop)
__device__ int    g_srcadj[NN * CAP];   // bucketed adjacency: sources per dest
__device__ float4 g_bases[NN * 16];     // [n][64] basis projections, PRE-SCALED by dis[n]
__device__ float  g_w[NN * 32];         // [n][32] combination weights
__device__ float4 g_h1[NN * 32];        // layer1 out [n][128]
__device__ float4 g_cls[NN];            // per-node {ps0, ps1, pd0, pd1}

__device__ __forceinline__ int eidx(const void* ei, int is64, long long i) {
    if (is64) return (int)((const long long*)ei)[i];
    return ((const int*)ei)[i];
}

// ---------------- init: zero counts + dtype detection ----------------
__global__ void k_init(const void* ei) {
    int i = blockIdx.x * blockDim.x + threadIdx.x;
    if (i < NN) g_cnt[i] = 0;
    if (i == 0) {
        const long long* p = (const long long*)ei;
        int is64 = 1;
        for (int k = 0; k < 64; k++) {
            long long v = p[k];
            if (v < 0 || v >= NN) { is64 = 0; break; }
        }
        g_is64 = is64;
    }
}

// ---------------- single-pass bucketed adjacency build ----------------
__global__ void k_fill(const void* __restrict__ ei) {
    int e = blockIdx.x * blockDim.x + threadIdx.x;
    if (e >= EE) return;
    int is64 = g_is64;
    unsigned r = (unsigned)eidx(ei, is64, e);
    unsigned c = (unsigned)eidx(ei, is64, (long long)EE + e);
    if (r >= NN || c >= NN) return;
    int slot = atomicAdd(&g_cnt[c], 1);
    if (slot < CAP) g_srcadj[c * CAP + slot] = (int)r;
}

// ---------------- node projection (persistent, shuffle + f32x2, vector w-loads) --------
// bases' = (x@Wb)*rsqrt(deg), w = x@Wc + bc. 300 blocks x 256 threads, ~49.5KB smem.
// Weights transposed output-major sWt[o][k], padded rows; one LDS.128 per output
// group per k4 (3 total) replaces 12 scalar LDS.
__global__ __launch_bounds__(256) void k_proj(
        const float* __restrict__ x_ext, int use_h1,
        const float* __restrict__ Wb, const float* __restrict__ Wc,
        const float* __restrict__ bc) {
    __shared__ float sWt[96][WPAD];   // ~49.5 KB, output-major
    for (int i = threadIdx.x; i < 128 * 96; i += 256) {
        int k = i >> 6;              // use 128*96 index space: k in [0,128), pair j in [0,96)
        int j = i & 63;              // j < 64 -> Wb col; else handled below
        (void)j;
        break;                       // (placeholder, replaced by real loader below)
    }
    // real loader: iterate over (o, k) pairs
    for (int i = threadIdx.x; i < 96 * 128; i += 256) {
        int o = i >> 7;              // output index 0..95
        int k = i & 127;             // k index 0..127
        float v = (o < 64) ? Wb[k * 64 + o] : Wc[k * 32 + (o - 64)];
        sWt[o][k] = v;
    }
    __syncthreads();

    const float* __restrict__ x = use_h1 ? (const float*)g_h1 : x_ext;

    int warp = threadIdx.x >> 5;
    int lane = threadIdx.x & 31;
    float bcv = bc[lane];

    for (int g = blockIdx.x * 8 + warp; g < NN / 4; g += PJB * 8) {
        int n0 = g * 4;

        float4 xr[4];
#pragma unroll
        for (int i = 0; i < 4; i++)
            xr[i] = *(const float4*)(x + (size_t)(n0 + i) * 128 + lane * 4);

        u64 a0p[2] = {0, 0}, a1p[2] = {0, 0}, a2p[2] = {0, 0};

#pragma unroll 4
        for (int k4 = 0; k4 < 32; k4++) {
            float4 xs[4];
#pragma unroll
            for (int i = 0; i < 4; i++) {
                xs[i].x = __shfl_sync(0xffffffffu, xr[i].x, k4);
                xs[i].y = __shfl_sync(0xffffffffu, xr[i].y, k4);
                xs[i].z = __shfl_sync(0xffffffffu, xr[i].z, k4);
                xs[i].w = __shfl_sync(0xffffffffu, xr[i].w, k4);
            }
            // vector weight loads: 4 k's per output group in one LDS.128
            float4 wq0 = *(const float4*)&sWt[lane][k4 * 4];
            float4 wq1 = *(const float4*)&sWt[lane + 32][k4 * 4];
            float4 wq2 = *(const float4*)&sWt[lane + 64][k4 * 4];
#pragma unroll
            for (int c = 0; c < 4; c++) {
                float w0 = (c == 0) ? wq0.x : (c == 1) ? wq0.y : (c == 2) ? wq0.z : wq0.w;
                float w1 = (c == 0) ? wq1.x : (c == 1) ? wq1.y : (c == 2) ? wq1.z : wq1.w;
                float w2 = (c == 0) ? wq2.x : (c == 1) ? wq2.y : (c == 2) ? wq2.z : wq2.w;
                u64 w0d = pk2(w0, w0), w1d = pk2(w1, w1), w2d = pk2(w2, w2);
                float xc0 = (c == 0) ? xs[0].x : (c == 1) ? xs[0].y : (c == 2) ? xs[0].z : xs[0].w;
                float xc1 = (c == 0) ? xs[1].x : (c == 1) ? xs[1].y : (c == 2) ? xs[1].z : xs[1].w;
                float xc2 = (c == 0) ? xs[2].x : (c == 1) ? xs[2].y : (c == 2) ? xs[2].z : xs[2].w;
                float xc3 = (c == 0) ? xs[3].x : (c == 1) ? xs[3].y : (c == 2) ? xs[3].z : xs[3].w;
                u64 xp0 = pk2(xc0, xc1), xp1 = pk2(xc2, xc3);
                a0p[0] = f2fma(xp0, w0d, a0p[0]);
                a0p[1] = f2fma(xp1, w0d, a0p[1]);
                a1p[0] = f2fma(xp0, w1d, a1p[0]);
                a1p[1] = f2fma(xp1, w1d, a1p[1]);
                a2p[0] = f2fma(xp0, w2d, a2p[0]);
                a2p[1] = f2fma(xp1, w2d, a2p[1]);
            }
        }

        float a0[4], a1[4], a2[4];
        upk2(a0p[0], a0[0], a0[1]); upk2(a0p[1], a0[2], a0[3]);
        upk2(a1p[0], a1[0], a1[1]); upk2(a1p[1], a1[2], a1[3]);
        upk2(a2p[0], a2[0], a2[1]); upk2(a2p[1], a2[2], a2[3]);

#pragma unroll
        for (int i = 0; i < 4; i++) {
            int n = n0 + i;
            float dis = rsqrtf((float)(g_cnt[n] + 1));
            float* bp = (float*)g_bases + (size_t)n * 64;
            bp[lane]      = a0[i] * dis;
            bp[lane + 32] = a1[i] * dis;
            g_w[(size_t)n * 32 + lane] = a2[i] + bcv;
        }
    }
}

// ---------------- aggregation (vectorized gather) + fused combine (+cls for layer 2) ----
// One warp per node; half-warp per edge, one float4 per lane.
__global__ void k_agg(const float* __restrict__ bias, const float* __restrict__ Wcls,
                      int mode) {
    __shared__ float sm[4][64];
    __shared__ float sWc[512];
    if (mode == 1) {
        for (int i = threadIdx.x; i < 512; i += 128) sWc[i] = Wcls[i];
    }
    __syncthreads();

    int wi = threadIdx.x >> 5;
    int lane = threadIdx.x & 31;
    int half = lane >> 4, hl = lane & 15;
    int n = blockIdx.x * 4 + wi;            // grid exact: NN/4 blocks

    int cnt = g_cnt[n];
    float dn = rsqrtf((float)(cnt + 1));
    const float4* __restrict__ bp4 = (const float4*)g_bases;
    const int* __restrict__ adj = g_srcadj + (size_t)n * CAP;

    float4 acc;
    if (half == 0) acc = bp4[(size_t)n * 16 + hl];   // self loop (bases' already *dis)
    else           acc = make_float4(0.f, 0.f, 0.f, 0.f);

    int end = (cnt < CAP) ? cnt : CAP;
    int i = 0;
    for (; i + 2 <= end; i += 2) {
        int s = adj[i + half];
        float4 v = bp4[(size_t)s * 16 + hl];
        acc.x += v.x; acc.y += v.y; acc.z += v.z; acc.w += v.w;
    }
    if (i < end && half == 0) {
        int s = adj[i];
        float4 v = bp4[(size_t)s * 16 + hl];
        acc.x += v.x; acc.y += v.y; acc.z += v.z; acc.w += v.w;
    }

    acc.x += __shfl_xor_sync(0xffffffffu, acc.x, 16);
    acc.y += __shfl_xor_sync(0xffffffffu, acc.y, 16);
    acc.z += __shfl_xor_sync(0xffffffffu, acc.z, 16);
    acc.w += __shfl_xor_sync(0xffffffffu, acc.w, 16);

    if (half == 0) {
        float4 sc = make_float4(acc.x * dn, acc.y * dn, acc.z * dn, acc.w * dn);
        ((float4*)sm[wi])[hl] = sc;
    }
    __syncwarp();

    float wreg = g_w[(size_t)n * 32 + lane];

    if (mode == 0) {
        float* __restrict__ out = (float*)g_h1 + (size_t)n * 128;
#pragma unroll
        for (int j = 0; j < 4; j++) {
            int o = lane + 32 * j;
            int h = o >> 4, f = o & 15;
            float v = bias[o];
#pragma unroll
            for (int b = 0; b < 4; b++) {
                float wb = __shfl_sync(0xffffffffu, wreg, h * 4 + b);
                v += wb * sm[wi][b * 16 + f];
            }
            out[o] = fmaxf(v, 0.f);
        }
    } else {
        float c0 = 0.f, c1 = 0.f, c2 = 0.f, c3 = 0.f;
#pragma unroll
        for (int j = 0; j < 4; j++) {
            int o = lane + 32 * j;
            int h = o >> 4, f = o & 15;
            float v = bias[o];
#pragma unroll
            for (int b = 0; b < 4; b++) {
                float wb = __shfl_sync(0xffffffffu, wreg, h * 4 + b);
                v += wb * sm[wi][b * 16 + f];
            }
            c0 += v * sWc[o * 2];
            c1 += v * sWc[o * 2 + 1];
            c2 += v * sWc[256 + o * 2];
            c3 += v * sWc[256 + o * 2 + 1];
        }
#pragma unroll
        for (int o = 16; o > 0; o >>= 1) {
            c0 += __shfl_down_sync(0xffffffffu, c0, o);
            c1 += __shfl_down_sync(0xffffffffu, c1, o);
            c2 += __shfl_down_sync(0xffffffffu, c2, o);
            c3 += __shfl_down_sync(0xffffffffu, c3, o);
        }
        if (lane == 0) g_cls[n] = make_float4(c0, c1, c2, c3);
    }
}

// ---------------- per-edge output (2 edges/thread): ps[src] + pd[dst] + bcls ------------
__global__ void k_edge_out(const void* __restrict__ ei,
                           const float* __restrict__ bcls,
                           float4* __restrict__ out2) {
    int p = blockIdx.x * blockDim.x + threadIdx.x;   // pair index, < EE/2
    if (p >= EE / 2) return;
    int is64 = g_is64;
    unsigned s0, s1, d0, d1;
    if (is64) {
        longlong2 sp = ((const longlong2*)ei)[p];
        longlong2 dp = ((const longlong2*)ei)[EE / 2 + p];
        s0 = (unsigned)sp.x; s1 = (unsigned)sp.y;
        d0 = (unsigned)dp.x; d1 = (unsigned)dp.y;
    } else {
        int2 sp = ((const int2*)ei)[p];
        int2 dp = ((const int2*)ei)[EE / 2 + p];
        s0 = (unsigned)sp.x; s1 = (unsigned)sp.y;
        d0 = (unsigned)dp.x; d1 = (unsigned)dp.y;
    }
    float b0 = bcls[0], b1 = bcls[1];
    float4 ps0 = (s0 < NN) ? g_cls[s0] : make_float4(0, 0, 0, 0);
    float4 pd0 = (d0 < NN) ? g_cls[d0] : make_float4(0, 0, 0, 0);
    float4 ps1 = (s1 < NN) ? g_cls[s1] : make_float4(0, 0, 0, 0);
    float4 pd1 = (d1 < NN) ? g_cls[d1] : make_float4(0, 0, 0, 0);
    out2[p] = make_float4(ps0.x + pd0.z + b0, ps0.y + pd0.w + b1,
                          ps1.x + pd1.z + b0, ps1.y + pd1.w + b1);
}

// ---------------- launch ----------------
extern "C" void kernel_launch(void* const* d_in, const int* in_sizes, int n_in,
                              void* d_out, int out_size) {
    const float* x    = (const float*)d_in[0];
    const void*  ei   = d_in[1];
    const float* Wb1  = (const float*)d_in[2];
    const float* Wc1  = (const float*)d_in[3];
    const float* bc1  = (const float*)d_in[4];
    const float* b1   = (const float*)d_in[5];
    const float* Wb2  = (const float*)d_in[6];
    const float* Wc2  = (const float*)d_in[7];
    const float* bc2  = (const float*)d_in[8];
    const float* b2   = (const float*)d_in[9];
    const float* Wcls = (const float*)d_in[10];
    const float* bcls = (const float*)d_in[11];
    float4*      out  = (float4*)d_out;

    // adjacency build (single pass, bucketed)
    k_init<<<NB, 256>>>(ei);
    k_fill<<<(EE + 255) / 256, 256>>>(ei);

    // layer 1
    k_proj<<<PJB, 256>>>(x, 0, Wb1, Wc1, bc1);
    k_agg<<<NN / 4, 128>>>(b1, Wcls, /*mode=*/0);

    // layer 2 (fused classifier projection; h2 never materialized)
    k_proj<<<PJB, 256>>>(x, 1, Wb2, Wc2, bc2);
    k_agg<<<NN / 4, 128>>>(b2, Wcls, /*mode=*/1);

    // edge classifier output
    k_edge_out<<<(EE / 2 + 255) / 256, 256>>>(ei, bcls, out);
}

// round 15
// speedup vs baseline: 1.0673x; 1.0673x over previous
#include <cuda_runtime.h>

#define NN 50000
#define EE 800000
#define CAP 96                    // per-node adjacency capacity (P(overflow) ~ e^-41)
#define PJB 300                   // persistent proj blocks

typedef unsigned long long u64;

__device__ __forceinline__ u64 pk2(float lo, float hi) {
    u64 d; asm("mov.b64 %0, {%1,%2};" : "=l"(d) : "f"(lo), "f"(hi)); return d;
}
__device__ __forceinline__ void upk2(u64 v, float& lo, float& hi) {
    asm("mov.b64 {%0,%1}, %2;" : "=f"(lo), "=f"(hi) : "l"(v));
}
__device__ __forceinline__ u64 f2fma(u64 a, u64 b, u64 c) {
    u64 d; asm("fma.rn.f32x2 %0, %1, %2, %3;" : "=l"(d) : "l"(a), "l"(b), "l"(c)); return d;
}

// ---------------- scratch (device globals; no allocation allowed) ----------------
// g_cnt starts zeroed (module load) and is re-zeroed by k_edge_out each launch,
// so every replay of the captured graph sees zeros without a dedicated init kernel.
__device__ int    g_is64;               // 1 if edge_index is int64 (published by k_fill)
__device__ int    g_cnt[NN];            // in-degree (w/o self loop)
__device__ int    g_srcadj[NN * CAP];   // bucketed adjacency: sources per dest
__device__ float4 g_bases[NN * 16];     // [n][64] basis projections, PRE-SCALED by dis[n]
__device__ float  g_w[NN * 32];         // [n][32] combination weights
__device__ float4 g_h1[NN * 32];        // layer1 out [n][128]
__device__ float4 g_cls[NN];            // per-node {ps0, ps1, pd0, pd1}

__device__ __forceinline__ int eidx(const void* ei, int is64, long long i) {
    if (is64) return (int)((const long long*)ei)[i];
    return ((const int*)ei)[i];
}

// ---------------- single-pass bucketed adjacency build + dtype detect ----------------
__global__ void k_fill(const void* __restrict__ ei) {
    __shared__ int s_is64;
    if (threadIdx.x == 0) {
        const long long* p = (const long long*)ei;
        int ok = 1;
#pragma unroll
        for (int k = 0; k < 64; k++) {
            long long v = p[k];
            ok &= (v >= 0 && v < NN) ? 1 : 0;
        }
        s_is64 = ok;
        if (blockIdx.x == 0) g_is64 = ok;   // for k_edge_out (later launch)
    }
    __syncthreads();
    int is64 = s_is64;

    int e = blockIdx.x * blockDim.x + threadIdx.x;
    if (e >= EE) return;
    unsigned r = (unsigned)eidx(ei, is64, e);
    unsigned c = (unsigned)eidx(ei, is64, (long long)EE + e);
    if (r >= NN || c >= NN) return;
    int slot = atomicAdd(&g_cnt[c], 1);
    if (slot < CAP) g_srcadj[c * CAP + slot] = (int)r;
}

// ---------------- node projection (persistent, shuffle + f32x2) ----------------
// bases' = (x@Wb)*rsqrt(deg), w = x@Wc + bc. 300 blocks x 256 threads, 48KB smem,
// warps grid-stride over 4-node groups; x rows in registers, broadcast via shuffle.
__global__ __launch_bounds__(256) void k_proj(
        const float* __restrict__ x_ext, int use_h1,
        const float* __restrict__ Wb, const float* __restrict__ Wc,
        const float* __restrict__ bc) {
    __shared__ float sW[128][96];   // 48 KB
    for (int i = threadIdx.x; i < 128 * 96; i += 256) {
        int k = i / 96, j = i - k * 96;
        sW[k][j] = (j < 64) ? Wb[k * 64 + j] : Wc[k * 32 + (j - 64)];
    }
    __syncthreads();

    const float* __restrict__ x = use_h1 ? (const float*)g_h1 : x_ext;

    int warp = threadIdx.x >> 5;
    int lane = threadIdx.x & 31;
    float bcv = bc[lane];

    for (int g = blockIdx.x * 8 + warp; g < NN / 4; g += PJB * 8) {
        int n0 = g * 4;

        float4 xr[4];
#pragma unroll
        for (int i = 0; i < 4; i++)
            xr[i] = *(const float4*)(x + (size_t)(n0 + i) * 128 + lane * 4);

        u64 a0p[2] = {0, 0}, a1p[2] = {0, 0}, a2p[2] = {0, 0};

#pragma unroll 4
        for (int k4 = 0; k4 < 32; k4++) {
            float4 xs[4];
#pragma unroll
            for (int i = 0; i < 4; i++) {
                xs[i].x = __shfl_sync(0xffffffffu, xr[i].x, k4);
                xs[i].y = __shfl_sync(0xffffffffu, xr[i].y, k4);
                xs[i].z = __shfl_sync(0xffffffffu, xr[i].z, k4);
                xs[i].w = __shfl_sync(0xffffffffu, xr[i].w, k4);
            }
#pragma unroll
            for (int c = 0; c < 4; c++) {
                int k = k4 * 4 + c;
                float w0 = sW[k][lane], w1 = sW[k][lane + 32], w2 = sW[k][lane + 64];
                u64 w0d = pk2(w0, w0), w1d = pk2(w1, w1), w2d = pk2(w2, w2);
                float xc0 = (c == 0) ? xs[0].x : (c == 1) ? xs[0].y : (c == 2) ? xs[0].z : xs[0].w;
                float xc1 = (c == 0) ? xs[1].x : (c == 1) ? xs[1].y : (c == 2) ? xs[1].z : xs[1].w;
                float xc2 = (c == 0) ? xs[2].x : (c == 1) ? xs[2].y : (c == 2) ? xs[2].z : xs[2].w;
                float xc3 = (c == 0) ? xs[3].x : (c == 1) ? xs[3].y : (c == 2) ? xs[3].z : xs[3].w;
                u64 xp0 = pk2(xc0, xc1), xp1 = pk2(xc2, xc3);
                a0p[0] = f2fma(xp0, w0d, a0p[0]);
                a0p[1] = f2fma(xp1, w0d, a0p[1]);
                a1p[0] = f2fma(xp0, w1d, a1p[0]);
                a1p[1] = f2fma(xp1, w1d, a1p[1]);
                a2p[0] = f2fma(xp0, w2d, a2p[0]);
                a2p[1] = f2fma(xp1, w2d, a2p[1]);
            }
        }

        float a0[4], a1[4], a2[4];
        upk2(a0p[0], a0[0], a0[1]); upk2(a0p[1], a0[2], a0[3]);
        upk2(a1p[0], a1[0], a1[1]); upk2(a1p[1], a1[2], a1[3]);
        upk2(a2p[0], a2[0], a2[1]); upk2(a2p[1], a2[2], a2[3]);

#pragma unroll
        for (int i = 0; i < 4; i++) {
            int n = n0 + i;
            float dis = rsqrtf((float)(g_cnt[n] + 1));
            float* bp = (float*)g_bases + (size_t)n * 64;
            bp[lane]      = a0[i] * dis;
            bp[lane + 32] = a1[i] * dis;
            g_w[(size_t)n * 32 + lane] = a2[i] + bcv;
        }
    }
}

// ---------------- aggregation (vectorized gather, 4-edge unrolled) + fused combine ------
// One warp per node; half-warp per edge, one float4 per lane; two independent
// accumulators to double memory-level parallelism.
__global__ void k_agg(const float* __restrict__ bias, const float* __restrict__ Wcls,
                      int mode) {
    __shared__ float sm[4][64];
    __shared__ float sWc[512];
    if (mode == 1) {
        for (int i = threadIdx.x; i < 512; i += 128) sWc[i] = Wcls[i];
    }
    __syncthreads();

    int wi = threadIdx.x >> 5;
    int lane = threadIdx.x & 31;
    int half = lane >> 4, hl = lane & 15;
    int n = blockIdx.x * 4 + wi;            // grid exact: NN/4 blocks

    int cnt = g_cnt[n];
    float dn = rsqrtf((float)(cnt + 1));
    const float4* __restrict__ bp4 = (const float4*)g_bases;
    const int* __restrict__ adj = g_srcadj + (size_t)n * CAP;

    float4 accA, accB = make_float4(0.f, 0.f, 0.f, 0.f);
    if (half == 0) accA = bp4[(size_t)n * 16 + hl];   // self loop (bases' already *dis)
    else           accA = make_float4(0.f, 0.f, 0.f, 0.f);

    int end = (cnt < CAP) ? cnt : CAP;
    int i = 0;
    for (; i + 4 <= end; i += 4) {
        int sA = adj[i + half];
        int sB = adj[i + 2 + half];
        float4 vA = bp4[(size_t)sA * 16 + hl];
        float4 vB = bp4[(size_t)sB * 16 + hl];
        accA.x += vA.x; accA.y += vA.y; accA.z += vA.z; accA.w += vA.w;
        accB.x += vB.x; accB.y += vB.y; accB.z += vB.z; accB.w += vB.w;
    }
    if (i + 2 <= end) {
        int s = adj[i + half];
        float4 v = bp4[(size_t)s * 16 + hl];
        accA.x += v.x; accA.y += v.y; accA.z += v.z; accA.w += v.w;
        i += 2;
    }
    if (i < end && half == 0) {
        int s = adj[i];
        float4 v = bp4[(size_t)s * 16 + hl];
        accB.x += v.x; accB.y += v.y; accB.z += v.z; accB.w += v.w;
    }

    float4 acc = make_float4(accA.x + accB.x, accA.y + accB.y,
                             accA.z + accB.z, accA.w + accB.w);

    acc.x += __shfl_xor_sync(0xffffffffu, acc.x, 16);
    acc.y += __shfl_xor_sync(0xffffffffu, acc.y, 16);
    acc.z += __shfl_xor_sync(0xffffffffu, acc.z, 16);
    acc.w += __shfl_xor_sync(0xffffffffu, acc.w, 16);

    if (half == 0) {
        float4 sc = make_float4(acc.x * dn, acc.y * dn, acc.z * dn, acc.w * dn);
        ((float4*)sm[wi])[hl] = sc;
    }
    __syncwarp();

    float wreg = g_w[(size_t)n * 32 + lane];

    if (mode == 0) {
        float* __restrict__ out = (float*)g_h1 + (size_t)n * 128;
#pragma unroll
        for (int j = 0; j < 4; j++) {
            int o = lane + 32 * j;
            int h = o >> 4, f = o & 15;
            float v = bias[o];
#pragma unroll
            for (int b = 0; b < 4; b++) {
                float wb = __shfl_sync(0xffffffffu, wreg, h * 4 + b);
                v += wb * sm[wi][b * 16 + f];
            }
            out[o] = fmaxf(v, 0.f);
        }
    } else {
        float c0 = 0.f, c1 = 0.f, c2 = 0.f, c3 = 0.f;
#pragma unroll
        for (int j = 0; j < 4; j++) {
            int o = lane + 32 * j;
            int h = o >> 4, f = o & 15;
            float v = bias[o];
#pragma unroll
            for (int b = 0; b < 4; b++) {
                float wb = __shfl_sync(0xffffffffu, wreg, h * 4 + b);
                v += wb * sm[wi][b * 16 + f];
            }
            c0 += v * sWc[o * 2];
            c1 += v * sWc[o * 2 + 1];
            c2 += v * sWc[256 + o * 2];
            c3 += v * sWc[256 + o * 2 + 1];
        }
#pragma unroll
        for (int o = 16; o > 0; o >>= 1) {
            c0 += __shfl_down_sync(0xffffffffu, c0, o);
            c1 += __shfl_down_sync(0xffffffffu, c1, o);
            c2 += __shfl_down_sync(0xffffffffu, c2, o);
            c3 += __shfl_down_sync(0xffffffffu, c3, o);
        }
        if (lane == 0) g_cls[n] = make_float4(c0, c1, c2, c3);
    }
}

// ---------------- per-edge output (2 edges/thread) + count reset for next replay --------
__global__ void k_edge_out(const void* __restrict__ ei,
                           const float* __restrict__ bcls,
                           float4* __restrict__ out2) {
    int p = blockIdx.x * blockDim.x + threadIdx.x;   // pair index, < EE/2
    if (p < NN) g_cnt[p] = 0;                        // reset for next graph replay
    if (p >= EE / 2) return;
    int is64 = g_is64;
    unsigned s0, s1, d0, d1;
    if (is64) {
        longlong2 sp = ((const longlong2*)ei)[p];
        longlong2 dp = ((const longlong2*)ei)[EE / 2 + p];
        s0 = (unsigned)sp.x; s1 = (unsigned)sp.y;
        d0 = (unsigned)dp.x; d1 = (unsigned)dp.y;
    } else {
        int2 sp = ((const int2*)ei)[p];
        int2 dp = ((const int2*)ei)[EE / 2 + p];
        s0 = (unsigned)sp.x; s1 = (unsigned)sp.y;
        d0 = (unsigned)dp.x; d1 = (unsigned)dp.y;
    }
    float b0 = bcls[0], b1 = bcls[1];
    float4 ps0 = (s0 < NN) ? g_cls[s0] : make_float4(0, 0, 0, 0);
    float4 pd0 = (d0 < NN) ? g_cls[d0] : make_float4(0, 0, 0, 0);
    float4 ps1 = (s1 < NN) ? g_cls[s1] : make_float4(0, 0, 0, 0);
    float4 pd1 = (d1 < NN) ? g_cls[d1] : make_float4(0, 0, 0, 0);
    out2[p] = make_float4(ps0.x + pd0.z + b0, ps0.y + pd0.w + b1,
                          ps1.x + pd1.z + b0, ps1.y + pd1.w + b1);
}

// ---------------- launch ----------------
extern "C" void kernel_launch(void* const* d_in, const int* in_sizes, int n_in,
                              void* d_out, int out_size) {
    const float* x    = (const float*)d_in[0];
    const void*  ei   = d_in[1];
    const float* Wb1  = (const float*)d_in[2];
    const float* Wc1  = (const float*)d_in[3];
    const float* bc1  = (const float*)d_in[4];
    const float* b1   = (const float*)d_in[5];
    const float* Wb2  = (const float*)d_in[6];
    const float* Wc2  = (const float*)d_in[7];
    const float* bc2  = (const float*)d_in[8];
    const float* b2   = (const float*)d_in[9];
    const float* Wcls = (const float*)d_in[10];
    const float* bcls = (const float*)d_in[11];
    float4*      out  = (float4*)d_out;

    // adjacency build (single pass, bucketed; counts pre-zeroed by previous replay)
    k_fill<<<(EE + 255) / 256, 256>>>(ei);

    // layer 1
    k_proj<<<PJB, 256>>>(x, 0, Wb1, Wc1, bc1);
    k_agg<<<NN / 4, 128>>>(b1, Wcls, /*mode=*/0);

    // layer 2 (fused classifier projection; h2 never materialized)
    k_proj<<<PJB, 256>>>(x, 1, Wb2, Wc2, bc2);
    k_agg<<<NN / 4, 128>>>(b2, Wcls, /*mode=*/1);

    // edge classifier output + count reset
    k_edge_out<<<(EE / 2 + 255) / 256, 256>>>(ei, bcls, out);
}